// round 3
// baseline (speedup 1.0000x reference)
#include <cuda_runtime.h>
#include <math.h>
#include <stdint.h>

#define BB   1024      // batch rows
#define NN   8192      // samples per row
#define MM   1800      // fold period
#define NB   140       // bpm bins
#define NBP  144       // padded bins
#define NCH  9         // m-chunks
#define MCH  200       // m per chunk

// ---------------- device scratch ----------------
__device__ float  d_fold[(size_t)BB * MM];              // folded hann-weighted pred
__device__ float2 d_part[(size_t)BB * NCH * NBP];       // [row][chunk][bin] (s,c)
__device__ float  d_tl[BB];                             // per-row (1 - pearson)
__device__ float  d_fl[BB];                             // per-row (ce + kl)
__device__ unsigned int d_done;

// ---------------- f32x2 helpers ----------------
__device__ __forceinline__ unsigned long long pk2(float lo, float hi) {
    unsigned long long r;
    asm("mov.b64 %0, {%1, %2};" : "=l"(r) : "f"(lo), "f"(hi));
    return r;
}
__device__ __forceinline__ void fma2(unsigned long long& d, unsigned long long a,
                                     unsigned long long b) {
    asm("fma.rn.f32x2 %0, %1, %2, %0;" : "+l"(d) : "l"(a), "l"(b));
}

// ---------------- warp helpers ----------------
__device__ __forceinline__ float wsum(float v) {
    #pragma unroll
    for (int o = 16; o; o >>= 1) v += __shfl_down_sync(0xffffffffu, v, o);
    return v;
}
__device__ __forceinline__ float wallsum(float v) {
    #pragma unroll
    for (int o = 16; o; o >>= 1) v += __shfl_xor_sync(0xffffffffu, v, o);
    return v;
}
__device__ __forceinline__ float wallmax(float v) {
    #pragma unroll
    for (int o = 16; o; o >>= 1) v = fmaxf(v, __shfl_xor_sync(0xffffffffu, v, o));
    return v;
}

// ---------------- K1: pearson sums + hann-weighted fold (hann inline) --------
__global__ void __launch_bounds__(256) k_fold(const float* __restrict__ x,
                                              const float* __restrict__ y) {
    __shared__ float shx[NN];          // 32 KB
    __shared__ float red[8][5];
    int b = blockIdx.x;
    int tid = threadIdx.x;
    int lane = tid & 31, warp = tid >> 5;

    if (b == 0 && tid == 0) d_done = 0;   // reset ticket for this replay

    const float4* xr = (const float4*)(x + (size_t)b * NN);
    const float4* yr = (const float4*)(y + (size_t)b * NN);

    float sx = 0.f, sy = 0.f, sxy = 0.f, sxx = 0.f, syy = 0.f;
    const float W = 3.8349520e-4f;     // pi/8191
    #pragma unroll
    for (int i = 0; i < 8; i++) {
        int q = tid + i * 256;         // float4 index
        float4 xv = xr[q];
        float4 yv = yr[q];
        sx += xv.x + xv.y + xv.z + xv.w;
        sy += yv.x + yv.y + yv.z + yv.w;
        sxy += xv.x * yv.x + xv.y * yv.y + xv.z * yv.z + xv.w * yv.w;
        sxx += xv.x * xv.x + xv.y * xv.y + xv.z * xv.z + xv.w * xv.w;
        syy += yv.x * yv.x + yv.y * yv.y + yv.z * yv.z + yv.w * yv.w;
        int n = 4 * q;
        float s0 = __sinf((float)(n)     * W);
        float s1 = __sinf((float)(n + 1) * W);
        float s2 = __sinf((float)(n + 2) * W);
        float s3 = __sinf((float)(n + 3) * W);
        float4 h = make_float4(xv.x * s0 * s0, xv.y * s1 * s1,
                               xv.z * s2 * s2, xv.w * s3 * s3);
        *(float4*)&shx[n] = h;
    }
    sx = wsum(sx); sy = wsum(sy); sxy = wsum(sxy); sxx = wsum(sxx); syy = wsum(syy);
    if (lane == 0) { red[warp][0]=sx; red[warp][1]=sy; red[warp][2]=sxy; red[warp][3]=sxx; red[warp][4]=syy; }
    __syncthreads();

    for (int m = tid; m < MM; m += 256) {
        float g = shx[m] + shx[m + 1800] + shx[m + 3600] + shx[m + 5400];
        if (m < NN - 4 * 1800) g += shx[m + 7200];
        d_fold[(size_t)b * MM + m] = g;
    }

    if (tid == 0) {
        double SX=0, SY=0, SXY=0, SXX=0, SYY=0;
        #pragma unroll
        for (int w = 0; w < 8; w++) {
            SX += red[w][0]; SY += red[w][1]; SXY += red[w][2];
            SXX += red[w][3]; SYY += red[w][4];
        }
        double num = (double)NN * SXY - SX * SY;
        double den = sqrt(((double)NN * SXX - SX * SX) * ((double)NN * SYY - SY * SY));
        d_tl[b] = (float)(1.0 - num / den);
    }
}

// ---------------- K2: folded NUDFT, f32x2-packed, in-kernel tables -----------
// grid (32 row-tiles, 9 m-chunks), block 144 = 36 tx * 4 ty
__global__ void __launch_bounds__(144, 2) k_dft() {
    __shared__ float sTab[8 * 2 * NBP];   // 8 m x 144 bins x (s,c)
    __shared__ float sG[8 * 36];          // 8 m x 32 rows (stride 36)

    int tile  = blockIdx.x;
    int chunk = blockIdx.y;
    int tid = threadIdx.x;
    int tx = tid % 36;
    int ty = tid / 36;

    int rowBase = tile * 32;
    int mBase = chunk * MCH;
    int bk = tid;                      // this thread's bin for table gen (0..143)
    int freq = 40 + bk;

    unsigned long long acc[8][4] = {};
    const float ASCALE = 3.4906585e-3f;   // 2*pi/1800

    for (int step = 0; step < MCH / 8; step++) {
        int m0 = mBase + step * 8;
        __syncthreads();
        // generate 8-m table slab: thread handles bin bk for all 8 m
        #pragma unroll
        for (int mi = 0; mi < 8; mi++) {
            float s = 0.f, c = 0.f;
            if (bk < NB) {
                int r = (freq * (m0 + mi)) % MM;      // < 2^19, exact
                if (r >= 900) r -= 1800;              // fold to [-900, 900)
                float ang = (float)r * ASCALE;        // |ang| <= pi
                __sincosf(ang, &s, &c);
            }
            sTab[mi * (2 * NBP) + 2 * bk]     = s;
            sTab[mi * (2 * NBP) + 2 * bk + 1] = c;
        }
        // fill g: 8 m x 32 rows
        for (int i = tid; i < 256; i += 144) {
            int r = i >> 3, mi = i & 7;
            sG[mi * 36 + r] = d_fold[(size_t)(rowBase + r) * MM + m0 + mi];
        }
        __syncthreads();

        #pragma unroll
        for (int mi = 0; mi < 8; mi++) {
            float4 g0 = *(const float4*)&sG[mi * 36 + 8 * ty];
            float4 g1 = *(const float4*)&sG[mi * 36 + 8 * ty + 4];
            const unsigned long long* trow =
                (const unsigned long long*)&sTab[mi * (2 * NBP)];
            unsigned long long p0 = trow[tx];
            unsigned long long p1 = trow[tx + 36];
            unsigned long long p2 = trow[tx + 72];
            unsigned long long p3 = trow[tx + 108];
            float gr[8] = {g0.x, g0.y, g0.z, g0.w, g1.x, g1.y, g1.z, g1.w};
            #pragma unroll
            for (int r = 0; r < 8; r++) {
                unsigned long long g2 = pk2(gr[r], gr[r]);
                fma2(acc[r][0], g2, p0);
                fma2(acc[r][1], g2, p1);
                fma2(acc[r][2], g2, p2);
                fma2(acc[r][3], g2, p3);
            }
        }
    }

    // partials: [row][chunk][bin]
    #pragma unroll
    for (int r = 0; r < 8; r++) {
        int row = rowBase + 8 * ty + r;
        unsigned long long* dst =
            (unsigned long long*)(d_part + ((size_t)row * NCH + chunk) * NBP);
        dst[tx]       = acc[r][0];
        dst[tx + 36]  = acc[r][1];
        dst[tx + 72]  = acc[r][2];
        dst[tx + 108] = acc[r][3];
    }
}

// ---------------- K3: partials -> row loss -> final scalar -------------------
// 128 blocks x 256 threads; warp = one row; last block computes final
__global__ void __launch_bounds__(256) k_loss(const int* __restrict__ hr,
                                              const int* __restrict__ epoch_p,
                                              float* __restrict__ out) {
    int tid = threadIdx.x;
    int lane = tid & 31, warp = tid >> 5;
    int row = blockIdx.x * 8 + warp;

    float sA[5] = {}, cA[5] = {};
    bool valid[5];
    #pragma unroll
    for (int j = 0; j < 5; j++) valid[j] = (lane + 32 * j < NB);

    const float2* pr = d_part + (size_t)row * NCH * NBP;
    #pragma unroll
    for (int ch = 0; ch < NCH; ch++) {
        #pragma unroll
        for (int j = 0; j < 5; j++) {
            if (valid[j]) {
                float2 v = pr[ch * NBP + lane + 32 * j];
                sA[j] += v.x; cA[j] += v.y;
            }
        }
    }

    float ca[5]; float tot = 0.f;
    #pragma unroll
    for (int j = 0; j < 5; j++) {
        ca[j] = sA[j] * sA[j] + cA[j] * cA[j];
        if (valid[j]) tot += ca[j];
    }
    tot = wallsum(tot);

    float logits[5]; float mx = -1e30f;
    #pragma unroll
    for (int j = 0; j < 5; j++) {
        logits[j] = ca[j] / tot;
        if (valid[j]) mx = fmaxf(mx, logits[j]);
    }
    mx = wallmax(mx);
    float se = 0.f;
    #pragma unroll
    for (int j = 0; j < 5; j++)
        if (valid[j]) se += expf(logits[j] - mx);
    se = wallsum(se);
    float lse = mx + logf(se);

    int h = hr[row];
    float lh = 0.f;
    #pragma unroll
    for (int j = 0; j < 5; j++) {
        int k = lane + 32 * j;
        if (valid[j] && k == h) lh = logits[j];
    }
    lh = wallsum(lh);
    float ce = lse - lh;

    float hf = (float)h;
    float klp = 0.f;
    #pragma unroll
    for (int j = 0; j < 5; j++) {
        if (valid[j]) {
            int k = lane + 32 * j;
            float dd = (float)k - hf;
            float t = expf(-0.5f * dd * dd) * 0.3989422804014327f;
            t = fmaxf(t, 1e-15f);
            float logp = logits[j] - lse;
            klp += expf(t) * (t - logp);
        }
    }
    klp = wallsum(klp);
    if (lane == 0) d_fl[row] = ce + klp / (float)NB;

    // ---- last-block final reduction ----
    __threadfence();
    __syncthreads();
    __shared__ unsigned int sTicket;
    if (tid == 0) sTicket = atomicAdd(&d_done, 1u);
    __syncthreads();
    if (sTicket != gridDim.x - 1) return;
    __threadfence();

    __shared__ float r1[8], r2[8];
    float a = 0.f, c = 0.f;
    #pragma unroll
    for (int i = 0; i < 4; i++) {
        a += d_tl[tid + 256 * i];
        c += d_fl[tid + 256 * i];
    }
    a = wsum(a); c = wsum(c);
    if (lane == 0) { r1[warp] = a; r2[warp] = c; }
    __syncthreads();
    if (tid == 0) {
        double TA = 0.0, TC = 0.0;
        #pragma unroll
        for (int w = 0; w < 8; w++) { TA += r1[w]; TC += r2[w]; }
        double tl = TA / (double)BB;
        double fl = TC / (double)BB;
        int epoch = epoch_p[0];
        double alpha, beta;
        if (epoch > 25) { alpha = 0.05; beta = 2.0; }
        else {
            alpha = 0.1 * pow(0.5, (double)epoch / 25.0);
            beta  = pow(2.0, (double)epoch / 25.0);
        }
        out[0] = (float)(alpha * tl + beta * fl);
    }
}

// ---------------- launch ----------------
extern "C" void kernel_launch(void* const* d_in, const int* in_sizes, int n_in,
                              void* d_out, int out_size) {
    const int*   epoch_p = nullptr;
    const float* xp = nullptr;
    const float* yp = nullptr;
    const int*   hrp = nullptr;
    for (int i = 0; i < n_in; i++) {
        if (in_sizes[i] == 1 && !epoch_p) epoch_p = (const int*)d_in[i];
        else if (in_sizes[i] == BB * NN) { if (!xp) xp = (const float*)d_in[i]; else yp = (const float*)d_in[i]; }
        else if (in_sizes[i] == BB) hrp = (const int*)d_in[i];
    }
    float* out = (float*)d_out;

    k_fold<<<BB, 256>>>(xp, yp);
    k_dft<<<dim3(32, NCH), 144>>>();
    k_loss<<<BB / 8, 256>>>(hrp, epoch_p, out);
    (void)out_size;
}

// round 4
// speedup vs baseline: 1.5183x; 1.5183x over previous
#include <cuda_runtime.h>
#include <math.h>
#include <stdint.h>

#define BB   1024      // batch rows
#define NN   8192      // samples per row
#define MM2  900       // half fold period (parity decimation)
#define NB   140       // bpm bins
#define NBP  144       // padded bins
#define NCH  9         // m-chunks
#define CHM  100       // m per chunk (9*100 = 900)
#define SLAB 10        // m per smem slab

// ---------------- device scratch ----------------
__device__ float  d_hann[NN];
__device__ float2 d_fold[(size_t)BB * MM2];             // (ge, go) per (row, m)
__device__ float2 d_part[(size_t)BB * NCH * NBP];       // [row][chunk][bin] (s,c)
__device__ float  d_tl[BB];                             // per-row (1 - pearson)
__device__ float  d_fl[BB];                             // per-row (ce + kl)
__device__ unsigned int d_done;

typedef unsigned long long ull;

// ---------------- f32x2 helpers ----------------
__device__ __forceinline__ ull pk2(float lo, float hi) {
    ull r;
    asm("mov.b64 %0, {%1, %2};" : "=l"(r) : "f"(lo), "f"(hi));
    return r;
}
__device__ __forceinline__ void fma2(ull& d, ull a, ull b) {
    asm("fma.rn.f32x2 %0, %1, %2, %0;" : "+l"(d) : "l"(a), "l"(b));
}

// ---------------- warp helpers ----------------
__device__ __forceinline__ float wsum(float v) {
    #pragma unroll
    for (int o = 16; o; o >>= 1) v += __shfl_down_sync(0xffffffffu, v, o);
    return v;
}
__device__ __forceinline__ float wallsum(float v) {
    #pragma unroll
    for (int o = 16; o; o >>= 1) v += __shfl_xor_sync(0xffffffffu, v, o);
    return v;
}
__device__ __forceinline__ float wallmax(float v) {
    #pragma unroll
    for (int o = 16; o; o >>= 1) v = fmaxf(v, __shfl_xor_sync(0xffffffffu, v, o));
    return v;
}

// ---------------- K0: hann table + ticket reset ----------------
__global__ void __launch_bounds__(256) k_init() {
    int n = blockIdx.x * 256 + threadIdx.x;
    if (n < NN) {
        float s = sinf((float)n * 3.8349520e-4f);   // pi/8191
        d_hann[n] = s * s;
    }
    if (n == 0) d_done = 0;
}

// ---------------- K1: pearson sums + parity fold (no smem row buffer) --------
__global__ void __launch_bounds__(256) k_fold(const float* __restrict__ x,
                                              const float* __restrict__ y) {
    __shared__ float red[8][5];
    int b = blockIdx.x;
    int tid = threadIdx.x;
    int lane = tid & 31, warp = tid >> 5;

    const float* xr = x + (size_t)b * NN;
    const float* yr = y + (size_t)b * NN;

    float sx = 0.f, sy = 0.f, sxy = 0.f, sxx = 0.f, syy = 0.f;

    #pragma unroll 1
    for (int m = tid; m < MM2; m += 256) {
        float ge = 0.f, go = 0.f;
        #pragma unroll
        for (int j = 0; j < 10; j++) {
            int n = m + 900 * j;
            if (j < 9 || n < NN) {
                float xv = xr[n], yv = yr[n];
                sx  += xv;       sy  += yv;
                sxy += xv * yv;  sxx += xv * xv;  syy += yv * yv;
                float hx = xv * d_hann[n];
                ge += hx;
                go += (j & 1) ? -hx : hx;
            }
        }
        d_fold[(size_t)b * MM2 + m] = make_float2(ge, go);
    }

    sx = wsum(sx); sy = wsum(sy); sxy = wsum(sxy); sxx = wsum(sxx); syy = wsum(syy);
    if (lane == 0) { red[warp][0]=sx; red[warp][1]=sy; red[warp][2]=sxy; red[warp][3]=sxx; red[warp][4]=syy; }
    __syncthreads();
    if (tid == 0) {
        double SX=0, SY=0, SXY=0, SXX=0, SYY=0;
        #pragma unroll
        for (int w = 0; w < 8; w++) {
            SX += red[w][0]; SY += red[w][1]; SXY += red[w][2];
            SXX += red[w][3]; SYY += red[w][4];
        }
        double num = (double)NN * SXY - SX * SY;
        double den = sqrt(((double)NN * SXX - SX * SX) * ((double)NN * SYY - SY * SY));
        d_tl[b] = (float)(1.0 - num / den);
    }
}

// ---------------- K2: 900-point parity NUDFT, f32x2, in-kernel tables --------
// grid (32 row-tiles, 9 chunks), block 288 = 36 tx * 8 ty; tile 4 rows x 4 bins
__global__ void __launch_bounds__(288, 2) k_dft() {
    __shared__ float sTab[SLAB * 2 * NBP];    // 10 m x 144 bins x (s,c) = 11.5 KB
    __shared__ float sGe[SLAB][32];           // 10 m x 32 rows
    __shared__ float sGo[SLAB][32];

    int tile  = blockIdx.x;
    int chunk = blockIdx.y;
    int tid = threadIdx.x;
    int tx = tid % 36;                 // bins tx, +36, +72, +108 (same parity)
    int ty = tid / 36;                 // rows 4*ty .. 4*ty+3

    int rowBase = tile * 32;
    int mBase = chunk * CHM;

    int bk  = tid % 144;               // table-gen bin
    int grp = tid / 144;               // table-gen m-half (0/1)
    int freq = 40 + bk;

    ull acc[4][4] = {};
    const float* gp = (tx & 1) ? &sGo[0][0] : &sGe[0][0];
    const float ASCALE = 3.4906585e-3f;   // 2*pi/1800

    for (int step = 0; step < CHM / SLAB; step++) {
        int m0 = mBase + step * SLAB;
        __syncthreads();
        // table slab: thread covers bin bk for 5 of the 10 m values
        #pragma unroll
        for (int i = 0; i < 5; i++) {
            int mi = grp * 5 + i;
            float s = 0.f, c = 0.f;
            if (bk < NB) {
                int r = (freq * (m0 + mi)) % 1800;    // exact integer reduction
                if (r >= 900) r -= 1800;              // fold to [-900, 900)
                __sincosf((float)r * ASCALE, &s, &c);
            }
            sTab[mi * (2 * NBP) + 2 * bk]     = s;
            sTab[mi * (2 * NBP) + 2 * bk + 1] = c;
        }
        // g slab: 160 threads each load one float4 = 2 m of (ge,go) for one row
        if (tid < 160) {
            int r = tid & 31, q = tid >> 5;           // q < 5
            float4 v = *(const float4*)(d_fold + (size_t)(rowBase + r) * MM2 + m0 + 2 * q);
            sGe[2 * q][r]     = v.x;  sGo[2 * q][r]     = v.y;
            sGe[2 * q + 1][r] = v.z;  sGo[2 * q + 1][r] = v.w;
        }
        __syncthreads();

        #pragma unroll
        for (int mi = 0; mi < SLAB; mi++) {
            float4 g = *(const float4*)&gp[mi * 32 + 4 * ty];
            const ull* trow = (const ull*)&sTab[mi * (2 * NBP)];
            ull p0 = trow[tx];
            ull p1 = trow[tx + 36];
            ull p2 = trow[tx + 72];
            ull p3 = trow[tx + 108];
            float gr[4] = {g.x, g.y, g.z, g.w};
            #pragma unroll
            for (int r = 0; r < 4; r++) {
                ull g2 = pk2(gr[r], gr[r]);
                fma2(acc[r][0], g2, p0);
                fma2(acc[r][1], g2, p1);
                fma2(acc[r][2], g2, p2);
                fma2(acc[r][3], g2, p3);
            }
        }
    }

    #pragma unroll
    for (int r = 0; r < 4; r++) {
        int row = rowBase + 4 * ty + r;
        ull* dst = (ull*)(d_part + ((size_t)row * NCH + chunk) * NBP);
        dst[tx]       = acc[r][0];
        dst[tx + 36]  = acc[r][1];
        dst[tx + 72]  = acc[r][2];
        dst[tx + 108] = acc[r][3];
    }
}

// ---------------- K3: partials -> row loss -> final scalar -------------------
__global__ void __launch_bounds__(256) k_loss(const int* __restrict__ hr,
                                              const int* __restrict__ epoch_p,
                                              float* __restrict__ out) {
    int tid = threadIdx.x;
    int lane = tid & 31, warp = tid >> 5;
    int row = blockIdx.x * 8 + warp;

    float sA[5] = {}, cA[5] = {};
    bool valid[5];
    #pragma unroll
    for (int j = 0; j < 5; j++) valid[j] = (lane + 32 * j < NB);

    const float2* pr = d_part + (size_t)row * NCH * NBP;
    #pragma unroll
    for (int ch = 0; ch < NCH; ch++) {
        #pragma unroll
        for (int j = 0; j < 5; j++) {
            if (valid[j]) {
                float2 v = pr[ch * NBP + lane + 32 * j];
                sA[j] += v.x; cA[j] += v.y;
            }
        }
    }

    float ca[5]; float tot = 0.f;
    #pragma unroll
    for (int j = 0; j < 5; j++) {
        ca[j] = sA[j] * sA[j] + cA[j] * cA[j];
        if (valid[j]) tot += ca[j];
    }
    tot = wallsum(tot);

    float logits[5]; float mx = -1e30f;
    #pragma unroll
    for (int j = 0; j < 5; j++) {
        logits[j] = ca[j] / tot;
        if (valid[j]) mx = fmaxf(mx, logits[j]);
    }
    mx = wallmax(mx);
    float se = 0.f;
    #pragma unroll
    for (int j = 0; j < 5; j++)
        if (valid[j]) se += expf(logits[j] - mx);
    se = wallsum(se);
    float lse = mx + logf(se);

    int h = hr[row];
    float lh = 0.f;
    #pragma unroll
    for (int j = 0; j < 5; j++) {
        int k = lane + 32 * j;
        if (valid[j] && k == h) lh = logits[j];
    }
    lh = wallsum(lh);
    float ce = lse - lh;

    float hf = (float)h;
    float klp = 0.f;
    #pragma unroll
    for (int j = 0; j < 5; j++) {
        if (valid[j]) {
            int k = lane + 32 * j;
            float dd = (float)k - hf;
            float t = expf(-0.5f * dd * dd) * 0.3989422804014327f;
            t = fmaxf(t, 1e-15f);
            float logp = logits[j] - lse;
            klp += expf(t) * (t - logp);
        }
    }
    klp = wallsum(klp);
    if (lane == 0) d_fl[row] = ce + klp / (float)NB;

    // ---- last-block final reduction ----
    __threadfence();
    __syncthreads();
    __shared__ unsigned int sTicket;
    if (tid == 0) sTicket = atomicAdd(&d_done, 1u);
    __syncthreads();
    if (sTicket != gridDim.x - 1) return;
    __threadfence();

    __shared__ float r1[8], r2[8];
    float a = 0.f, c = 0.f;
    #pragma unroll
    for (int i = 0; i < 4; i++) {
        a += d_tl[tid + 256 * i];
        c += d_fl[tid + 256 * i];
    }
    a = wsum(a); c = wsum(c);
    if (lane == 0) { r1[warp] = a; r2[warp] = c; }
    __syncthreads();
    if (tid == 0) {
        double TA = 0.0, TC = 0.0;
        #pragma unroll
        for (int w = 0; w < 8; w++) { TA += r1[w]; TC += r2[w]; }
        double tl = TA / (double)BB;
        double fl = TC / (double)BB;
        int epoch = epoch_p[0];
        double alpha, beta;
        if (epoch > 25) { alpha = 0.05; beta = 2.0; }
        else {
            alpha = 0.1 * pow(0.5, (double)epoch / 25.0);
            beta  = pow(2.0, (double)epoch / 25.0);
        }
        out[0] = (float)(alpha * tl + beta * fl);
    }
}

// ---------------- launch ----------------
extern "C" void kernel_launch(void* const* d_in, const int* in_sizes, int n_in,
                              void* d_out, int out_size) {
    const int*   epoch_p = nullptr;
    const float* xp = nullptr;
    const float* yp = nullptr;
    const int*   hrp = nullptr;
    for (int i = 0; i < n_in; i++) {
        if (in_sizes[i] == 1 && !epoch_p) epoch_p = (const int*)d_in[i];
        else if (in_sizes[i] == BB * NN) { if (!xp) xp = (const float*)d_in[i]; else yp = (const float*)d_in[i]; }
        else if (in_sizes[i] == BB) hrp = (const int*)d_in[i];
    }
    float* out = (float*)d_out;

    k_init<<<(NN + 255) / 256, 256>>>();
    k_fold<<<BB, 256>>>(xp, yp);
    k_dft<<<dim3(32, NCH), 288>>>();
    k_loss<<<BB / 8, 256>>>(hrp, epoch_p, out);
    (void)out_size;
}